// round 14
// baseline (speedup 1.0000x reference)
#include <cuda_runtime.h>
#include <cuda_bf16.h>
#include <stdint.h>

#define NCC   64
#define NCPC  8
#define FINF  3.402823466e38f
#define FR    68                      // frag-table row stride in u32 (272B, 16B-aligned)

typedef unsigned long long u64;

// ---------- f32x2 helpers (inner stage, R9/R13-proven exact path) ----------
__device__ __forceinline__ u64 ffma2(u64 a, u64 b, u64 c) {
    u64 d; asm("fma.rn.f32x2 %0, %1, %2, %3;" : "=l"(d) : "l"(a), "l"(b), "l"(c)); return d;
}
__device__ __forceinline__ u64 fmul2(u64 a, u64 b) {
    u64 d; asm("mul.rn.f32x2 %0, %1, %2;" : "=l"(d) : "l"(a), "l"(b)); return d;
}
__device__ __forceinline__ float hsum2(u64 v) {
    float lo, hi; asm("mov.b64 {%0, %1}, %2;" : "=f"(lo), "=f"(hi) : "l"(v)); return lo + hi;
}
__device__ __forceinline__ u64 packf2(float lo, float hi) {
    u64 r; asm("mov.b64 %0, {%1, %2};" : "=l"(r) : "f"(lo), "f"(hi)); return r;
}

// ---------- 3-way bf16 split (carries ~24 mantissa bits) ----------
__device__ __forceinline__ void split3(float vx, float vy,
                                       uint32_t& s1, uint32_t& s2, uint32_t& s3) {
    __nv_bfloat162 h1 = __float22bfloat162_rn(make_float2(vx, vy));
    float2 f1 = __bfloat1622float2(h1);
    float rx = vx - f1.x, ry = vy - f1.y;
    __nv_bfloat162 h2 = __float22bfloat162_rn(make_float2(rx, ry));
    float2 f2 = __bfloat1622float2(h2);
    __nv_bfloat162 h3 = __float22bfloat162_rn(make_float2(rx - f2.x, ry - f2.y));
    s1 = *reinterpret_cast<uint32_t*>(&h1);
    s2 = *reinterpret_cast<uint32_t*>(&h2);
    s3 = *reinterpret_cast<uint32_t*>(&h3);
}
__device__ __forceinline__ void mma16816(float& d0, float& d1, float& d2, float& d3,
                                         uint32_t a0, uint32_t a1, uint32_t a2, uint32_t a3,
                                         uint32_t b0, uint32_t b1) {
    asm volatile("mma.sync.aligned.m16n8k16.row.col.f32.bf16.bf16.f32 "
                 "{%0,%1,%2,%3}, {%4,%5,%6,%7}, {%8,%9}, {%0,%1,%2,%3};"
                 : "+f"(d0), "+f"(d1), "+f"(d2), "+f"(d3)
                 : "r"(a0), "r"(a1), "r"(a2), "r"(a3), "r"(b0), "r"(b1));
}

// monotone float->uint map packed with index: u64 min == (dist, then smaller idx)
__device__ __forceinline__ u64 dkey(float f, int i) {
    uint32_t b = __float_as_uint(f);
    uint32_t m = b ^ ((uint32_t)((int)b >> 31) | 0x80000000u);
    return ((u64)m << 32) | (uint32_t)i;
}
__device__ __forceinline__ u64 umin64(u64 a, u64 b) { return a < b ? a : b; }

__global__ void __launch_bounds__(256, 3)
cluster_hmma_kernel(const float* __restrict__ x,
                    const float* __restrict__ co,
                    const float* __restrict__ ci,
                    float* __restrict__ out, int n)
{
    __shared__ float s_on[NCC];
    __shared__ float s_inn[NCC * NCPC];
    // B-fragment table: per lane, 8 blocks x {b1k0,b1k1,b2k0,b2k1,b3k0,b3k1,nrm0,nrm1}
    __shared__ __align__(16) uint32_t s_frag[32 * FR];

    const int tid  = threadIdx.x;
    const int lane = tid & 31;
    const int wid  = tid >> 5;
    const int kq   = (lane & 3) * 2;      // k-pair offset of this lane's fragments
    const int nB   = lane >> 2;           // B column within an 8-center block

    // norms (exact fp32, sequential d — matches reference decisions)
    if (tid < NCC) {
        const float* cp = co + tid * 16;
        float s = 0.f;
        #pragma unroll
        for (int d = 0; d < 16; d++) s += cp[d] * cp[d];
        s_on[tid] = s;
    }
    for (int e = tid; e < NCC * NCPC; e += 256) {
        const float* cp = ci + (size_t)e * 16;
        float s = 0.f;
        #pragma unroll
        for (int d = 0; d < 16; d++) s += cp[d] * cp[d];
        s_inn[e] = s;
    }
    __syncthreads();

    // Warp 0 builds the lane-indexed B-fragment table (identical for all warps).
    if (wid == 0) {
        #pragma unroll
        for (int b = 0; b < 8; b++) {
            const float* cb = co + (size_t)(8 * b + nB) * 16;
            float2 g0 = *(const float2*)(cb + kq);
            float2 g1 = *(const float2*)(cb + kq + 8);
            uint32_t p1k0, p2k0, p3k0, p1k1, p2k1, p3k1;
            split3(g0.x, g0.y, p1k0, p2k0, p3k0);
            split3(g1.x, g1.y, p1k1, p2k1, p3k1);
            uint32_t* row = s_frag + lane * FR + b * 8;
            *(uint4*)(row)     = make_uint4(p1k0, p1k1, p2k0, p2k1);
            *(uint4*)(row + 4) = make_uint4(p3k0, p3k1,
                                            __float_as_uint(s_on[8 * b + kq]),
                                            __float_as_uint(s_on[8 * b + kq + 1]));
        }
    }
    __syncthreads();

    const uint32_t* myfrag = s_frag + lane * FR;
    const int ntile = (n + 15) >> 4;
    const int gw = blockIdx.x * 8 + wid;
    const int nw = gridDim.x * 8;
    const u64 neg2 = packf2(-2.f, -2.f);

    for (int t = gw; t < ntile; t += nw) {
        const int base = t * 16;

        // ---- A fragments: rows = points, values = -2*x1, 3-way split ----
        int rlo = base + (lane >> 2);     if (rlo >= n) rlo = n - 1;
        int rhi = rlo + 8;                if (rhi >= n) rhi = n - 1;
        const float* xl = x + (size_t)rlo * 32;
        const float* xh = x + (size_t)rhi * 32;
        float2 fa = *(const float2*)(xl + kq);
        float2 fb = *(const float2*)(xh + kq);
        float2 fc = *(const float2*)(xl + kq + 8);
        float2 fd = *(const float2*)(xh + kq + 8);

        uint32_t a1[4], a2[4], a3[4];
        split3(-2.f * fa.x, -2.f * fa.y, a1[0], a2[0], a3[0]);
        split3(-2.f * fb.x, -2.f * fb.y, a1[1], a2[1], a3[1]);
        split3(-2.f * fc.x, -2.f * fc.y, a1[2], a2[2], a3[2]);
        split3(-2.f * fd.x, -2.f * fd.y, a1[3], a2[3], a3[3]);

        // ---- outer distances: 6-term split MMA (same order as R13) ----
        float bdl = FINF, bdh = FINF;
        int   bcl = 0,    bch = 0;

        #pragma unroll
        for (int b = 0; b < 8; b++) {
            uint4 f0 = *(const uint4*)(myfrag + b * 8);       // b1k0,b1k1,b2k0,b2k1
            uint4 f1 = *(const uint4*)(myfrag + b * 8 + 4);   // b3k0,b3k1,nrm0,nrm1

            float d0 = 0.f, d1 = 0.f, d2 = 0.f, d3 = 0.f;
            mma16816(d0,d1,d2,d3, a3[0],a3[1],a3[2],a3[3], f0.x, f0.y); // a3*b1
            mma16816(d0,d1,d2,d3, a2[0],a2[1],a2[2],a2[3], f0.z, f0.w); // a2*b2
            mma16816(d0,d1,d2,d3, a1[0],a1[1],a1[2],a1[3], f1.x, f1.y); // a1*b3
            mma16816(d0,d1,d2,d3, a2[0],a2[1],a2[2],a2[3], f0.x, f0.y); // a2*b1
            mma16816(d0,d1,d2,d3, a1[0],a1[1],a1[2],a1[3], f0.z, f0.w); // a1*b2
            mma16816(d0,d1,d2,d3, a1[0],a1[1],a1[2],a1[3], f0.x, f0.y); // a1*b1

            float n0 = __uint_as_float(f1.z), n1 = __uint_as_float(f1.w);
            float e0 = d0 + n0, e1 = d1 + n1;   // row lo, cols 8b+kq, +1
            float e2 = d2 + n0, e3 = d3 + n1;   // row hi
            int c0 = 8 * b + kq, c1 = c0 + 1;
            if (e0 < bdl) { bdl = e0; bcl = c0; }
            if (e1 < bdl) { bdl = e1; bcl = c1; }
            if (e2 < bdh) { bdh = e2; bch = c0; }
            if (e3 < bdh) { bdh = e3; bch = c1; }
        }

        // quad reduction over the 4 lanes holding this row's columns
        u64 klo = dkey(bdl, bcl), khi = dkey(bdh, bch);
        klo = umin64(klo, __shfl_xor_sync(0xffffffffu, klo, 1));
        khi = umin64(khi, __shfl_xor_sync(0xffffffffu, khi, 1));
        klo = umin64(klo, __shfl_xor_sync(0xffffffffu, klo, 2));
        khi = umin64(khi, __shfl_xor_sync(0xffffffffu, khi, 2));
        uint32_t col_lo = (uint32_t)klo, col_hi = (uint32_t)khi;

        // ---- redistribute: 2 threads per point for the inner stage ----
        const int r  = lane >> 1;                 // 0..15
        const int pt = base + r;
        const bool valid = (pt < n);
        const int  ptc = valid ? pt : (n - 1);
        const int  src = (r & 7) * 4;             // lane holding row r's argmin
        uint32_t blo = __shfl_sync(0xffffffffu, col_lo, src);
        uint32_t bhi = __shfl_sync(0xffffffffu, col_hi, src);
        const int bo = (r < 8) ? (int)blo : (int)bhi;

        // ---- inner argmin: acc = (norm,0) + sum (-2x2)*c  (R13-exact) ----
        const ulonglong2* q = (const ulonglong2*)(x + (size_t)ptc * 32) + 4;
        ulonglong2 y0 = q[0], y1 = q[1], y2 = q[2], y3 = q[3];
        u64 py[8] = {fmul2(y0.x, neg2), fmul2(y0.y, neg2), fmul2(y1.x, neg2), fmul2(y1.y, neg2),
                     fmul2(y2.x, neg2), fmul2(y2.y, neg2), fmul2(y3.x, neg2), fmul2(y3.y, neg2)};

        const int k0 = (lane & 1) * 4;            // this thread's 4 sub-centers
        const ulonglong2* cb = (const ulonglong2*)(ci + (size_t)(bo * NCPC + k0) * 16);
        const float* nb = s_inn + bo * NCPC + k0;

        float bd = FINF; int bk = k0;
        #pragma unroll
        for (int j = 0; j < 4; j++) {
            ulonglong2 r0 = cb[4*j], r1 = cb[4*j+1], r2 = cb[4*j+2], r3 = cb[4*j+3];
            u64 s = ffma2(py[0], r0.x, packf2(nb[j], 0.f));
            s = ffma2(py[1], r0.y, s);
            s = ffma2(py[2], r1.x, s);
            s = ffma2(py[3], r1.y, s);
            s = ffma2(py[4], r2.x, s);
            s = ffma2(py[5], r2.y, s);
            s = ffma2(py[6], r3.x, s);
            s = ffma2(py[7], r3.y, s);
            float dd = hsum2(s);
            if (dd < bd) { bd = dd; bk = k0 + j; }
        }

        u64 kk = dkey(bd, bo * NCPC + bk);
        kk = umin64(kk, __shfl_xor_sync(0xffffffffu, kk, 1));
        if (valid && (lane & 1) == 0)
            out[pt] = (float)(uint32_t)kk;
    }
}

extern "C" void kernel_launch(void* const* d_in, const int* in_sizes, int n_in,
                              void* d_out, int out_size)
{
    // Bind inputs by unique element counts (robust to metadata ordering).
    const float* x  = 0; const float* co = 0; const float* ci = 0;
    long long x_elems = 0;
    for (int i = 0; i < n_in; i++) {
        int sz = in_sizes[i];
        if (sz == NCC * 16)              co = (const float*)d_in[i];
        else if (sz == NCC * NCPC * 16)  ci = (const float*)d_in[i];
        else { x = (const float*)d_in[i]; x_elems = sz; }
    }
    if (!x)  { x  = (const float*)d_in[0]; x_elems = in_sizes[0]; }
    if (!co)   co = (const float*)d_in[1];
    if (!ci)   ci = (const float*)d_in[2];

    float* out = (float*)d_out;
    int n = (int)(x_elems / 32);
    if (n <= 0 || n > out_size) n = out_size;

    int blocks = 444;   // 148 SMs x 3 CTAs of 256 thr; grid-stride over 16-pt tiles
    cluster_hmma_kernel<<<blocks, 256>>>(x, co, ci, out, n);
}

// round 15
// speedup vs baseline: 1.6414x; 1.6414x over previous
#include <cuda_runtime.h>
#include <cuda_bf16.h>
#include <stdint.h>

#define NCC   64
#define NCPC  8
#define FINF  3.402823466e38f
#define FR    68                      // frag-table row stride in u32 (272B, 16B-aligned)
#define ISTRIDE 140                   // inner o-row: 128 data + 8 norms + 4 pad floats

typedef unsigned long long u64;

// ---------- f32x2 helpers (inner stage, R9-proven exact path) ----------
__device__ __forceinline__ u64 ffma2(u64 a, u64 b, u64 c) {
    u64 d; asm("fma.rn.f32x2 %0, %1, %2, %3;" : "=l"(d) : "l"(a), "l"(b), "l"(c)); return d;
}
__device__ __forceinline__ u64 fmul2(u64 a, u64 b) {
    u64 d; asm("mul.rn.f32x2 %0, %1, %2;" : "=l"(d) : "l"(a), "l"(b)); return d;
}
__device__ __forceinline__ float hsum2(u64 v) {
    float lo, hi; asm("mov.b64 {%0, %1}, %2;" : "=f"(lo), "=f"(hi) : "l"(v)); return lo + hi;
}
__device__ __forceinline__ u64 packf2(float lo, float hi) {
    u64 r; asm("mov.b64 %0, {%1, %2};" : "=l"(r) : "f"(lo), "f"(hi)); return r;
}

// ---------- 3-way bf16 split (carries ~24 mantissa bits) ----------
__device__ __forceinline__ void split3(float vx, float vy,
                                       uint32_t& s1, uint32_t& s2, uint32_t& s3) {
    __nv_bfloat162 h1 = __float22bfloat162_rn(make_float2(vx, vy));
    float2 f1 = __bfloat1622float2(h1);
    float rx = vx - f1.x, ry = vy - f1.y;
    __nv_bfloat162 h2 = __float22bfloat162_rn(make_float2(rx, ry));
    float2 f2 = __bfloat1622float2(h2);
    __nv_bfloat162 h3 = __float22bfloat162_rn(make_float2(rx - f2.x, ry - f2.y));
    s1 = *reinterpret_cast<uint32_t*>(&h1);
    s2 = *reinterpret_cast<uint32_t*>(&h2);
    s3 = *reinterpret_cast<uint32_t*>(&h3);
}
__device__ __forceinline__ void mma16816(float& d0, float& d1, float& d2, float& d3,
                                         uint32_t a0, uint32_t a1, uint32_t a2, uint32_t a3,
                                         uint32_t b0, uint32_t b1) {
    asm volatile("mma.sync.aligned.m16n8k16.row.col.f32.bf16.bf16.f32 "
                 "{%0,%1,%2,%3}, {%4,%5,%6,%7}, {%8,%9}, {%0,%1,%2,%3};"
                 : "+f"(d0), "+f"(d1), "+f"(d2), "+f"(d3)
                 : "r"(a0), "r"(a1), "r"(a2), "r"(a3), "r"(b0), "r"(b1));
}

// monotone float->uint map packed with index: u64 min == (dist, then smaller idx)
__device__ __forceinline__ u64 dkey(float f, int i) {
    uint32_t b = __float_as_uint(f);
    uint32_t m = b ^ ((uint32_t)((int)b >> 31) | 0x80000000u);
    return ((u64)m << 32) | (uint32_t)i;
}
__device__ __forceinline__ u64 umin64(u64 a, u64 b) { return a < b ? a : b; }

__global__ void __launch_bounds__(256, 3)
cluster_hmma_kernel(const float* __restrict__ x,
                    const float* __restrict__ co,
                    const float* __restrict__ ci,
                    float* __restrict__ out, int n)
{
    __shared__ float s_on[NCC];
    // inner centers, R9 layout: row o = {128 data floats | 8 norms | 4 pad}
    __shared__ __align__(16) float s_in[NCC * ISTRIDE];
    // B-fragment table: per lane, 8 blocks x {b1k0,b1k1,b2k0,b2k1,b3k0,b3k1,nrm0,nrm1}
    __shared__ __align__(16) uint32_t s_frag[32 * FR];

    const int tid  = threadIdx.x;
    const int lane = tid & 31;
    const int wid  = tid >> 5;
    const int kq   = (lane & 3) * 2;      // k-pair offset of this lane's fragments
    const int nB   = lane >> 2;           // B column within an 8-center block

    // outer norms (exact fp32, sequential d — matches reference decisions)
    if (tid < NCC) {
        const float* cp = co + tid * 16;
        float s = 0.f;
        #pragma unroll
        for (int d = 0; d < 16; d++) s += cp[d] * cp[d];
        s_on[tid] = s;
    }
    // inner centers -> smem (coalesced), then norms into the pad region
    for (int idx = tid; idx < NCC * NCPC * 16; idx += 256) {
        int o = idx >> 7, r = idx & 127;
        s_in[o * ISTRIDE + r] = ci[idx];
    }
    __syncthreads();
    for (int e = tid; e < NCC * NCPC; e += 256) {
        int o = e >> 3, k = e & 7;
        const float* cp = s_in + o * ISTRIDE + k * 16;
        float s = 0.f;
        #pragma unroll
        for (int d = 0; d < 16; d++) s += cp[d] * cp[d];
        s_in[o * ISTRIDE + 128 + k] = s;
    }

    // Warp 0 builds the lane-indexed B-fragment table (identical for all warps).
    if (wid == 0) {
        #pragma unroll
        for (int b = 0; b < 8; b++) {
            const float* cb = co + (size_t)(8 * b + nB) * 16;
            float2 g0 = *(const float2*)(cb + kq);
            float2 g1 = *(const float2*)(cb + kq + 8);
            uint32_t p1k0, p2k0, p3k0, p1k1, p2k1, p3k1;
            split3(g0.x, g0.y, p1k0, p2k0, p3k0);
            split3(g1.x, g1.y, p1k1, p2k1, p3k1);
            uint32_t* row = s_frag + lane * FR + b * 8;
            *(uint4*)(row)     = make_uint4(p1k0, p1k1, p2k0, p2k1);
            *(uint4*)(row + 4) = make_uint4(p3k0, p3k1,
                                            __float_as_uint(s_on[8 * b + kq]),
                                            __float_as_uint(s_on[8 * b + kq + 1]));
        }
    }
    __syncthreads();

    const uint32_t* myfrag = s_frag + lane * FR;
    const int ntile = (n + 15) >> 4;
    const int gw = blockIdx.x * 8 + wid;
    const int nw = gridDim.x * 8;
    const u64 neg2 = packf2(-2.f, -2.f);

    for (int t = gw; t < ntile; t += nw) {
        const int base = t * 16;

        // ---- A fragments: rows = points, values = -2*x1, 3-way split ----
        int rlo = base + (lane >> 2);     if (rlo >= n) rlo = n - 1;
        int rhi = rlo + 8;                if (rhi >= n) rhi = n - 1;
        const float* xl = x + (size_t)rlo * 32;
        const float* xh = x + (size_t)rhi * 32;
        float2 fa = *(const float2*)(xl + kq);
        float2 fb = *(const float2*)(xh + kq);
        float2 fc = *(const float2*)(xl + kq + 8);
        float2 fd = *(const float2*)(xh + kq + 8);

        uint32_t a1[4], a2[4], a3[4];
        split3(-2.f * fa.x, -2.f * fa.y, a1[0], a2[0], a3[0]);
        split3(-2.f * fb.x, -2.f * fb.y, a1[1], a2[1], a3[1]);
        split3(-2.f * fc.x, -2.f * fc.y, a1[2], a2[2], a3[2]);
        split3(-2.f * fd.x, -2.f * fd.y, a1[3], a2[3], a3[3]);

        // ---- outer distances: 6-term split MMA (same order as R13/R14) ----
        float bdl = FINF, bdh = FINF;
        int   bcl = 0,    bch = 0;

        #pragma unroll
        for (int b = 0; b < 8; b++) {
            uint4 f0 = *(const uint4*)(myfrag + b * 8);       // b1k0,b1k1,b2k0,b2k1
            uint4 f1 = *(const uint4*)(myfrag + b * 8 + 4);   // b3k0,b3k1,nrm0,nrm1

            float d0 = 0.f, d1 = 0.f, d2 = 0.f, d3 = 0.f;
            mma16816(d0,d1,d2,d3, a3[0],a3[1],a3[2],a3[3], f0.x, f0.y); // a3*b1
            mma16816(d0,d1,d2,d3, a2[0],a2[1],a2[2],a2[3], f0.z, f0.w); // a2*b2
            mma16816(d0,d1,d2,d3, a1[0],a1[1],a1[2],a1[3], f1.x, f1.y); // a1*b3
            mma16816(d0,d1,d2,d3, a2[0],a2[1],a2[2],a2[3], f0.x, f0.y); // a2*b1
            mma16816(d0,d1,d2,d3, a1[0],a1[1],a1[2],a1[3], f0.z, f0.w); // a1*b2
            mma16816(d0,d1,d2,d3, a1[0],a1[1],a1[2],a1[3], f0.x, f0.y); // a1*b1

            float n0 = __uint_as_float(f1.z), n1 = __uint_as_float(f1.w);
            float e0 = d0 + n0, e1 = d1 + n1;   // row lo, cols 8b+kq, +1
            float e2 = d2 + n0, e3 = d3 + n1;   // row hi
            int c0 = 8 * b + kq, c1 = c0 + 1;
            if (e0 < bdl) { bdl = e0; bcl = c0; }
            if (e1 < bdl) { bdl = e1; bcl = c1; }
            if (e2 < bdh) { bdh = e2; bch = c0; }
            if (e3 < bdh) { bdh = e3; bch = c1; }
        }

        // quad reduction over the 4 lanes holding this row's columns
        u64 klo = dkey(bdl, bcl), khi = dkey(bdh, bch);
        klo = umin64(klo, __shfl_xor_sync(0xffffffffu, klo, 1));
        khi = umin64(khi, __shfl_xor_sync(0xffffffffu, khi, 1));
        klo = umin64(klo, __shfl_xor_sync(0xffffffffu, klo, 2));
        khi = umin64(khi, __shfl_xor_sync(0xffffffffu, khi, 2));
        uint32_t col_lo = (uint32_t)klo, col_hi = (uint32_t)khi;

        // ---- redistribute: 2 threads per point for the inner stage ----
        const int r  = lane >> 1;                 // 0..15
        const int pt = base + r;
        const bool valid = (pt < n);
        const int  ptc = valid ? pt : (n - 1);
        const int  src = (r & 7) * 4;             // lane holding row r's argmin
        uint32_t blo = __shfl_sync(0xffffffffu, col_lo, src);
        uint32_t bhi = __shfl_sync(0xffffffffu, col_hi, src);
        const int bo = (r < 8) ? (int)blo : (int)bhi;

        // ---- inner argmin: acc = (norm,0) + sum (-2x2)*c, centers from SMEM ----
        const ulonglong2* q = (const ulonglong2*)(x + (size_t)ptc * 32) + 4;
        ulonglong2 y0 = q[0], y1 = q[1], y2 = q[2], y3 = q[3];
        u64 py[8] = {fmul2(y0.x, neg2), fmul2(y0.y, neg2), fmul2(y1.x, neg2), fmul2(y1.y, neg2),
                     fmul2(y2.x, neg2), fmul2(y2.y, neg2), fmul2(y3.x, neg2), fmul2(y3.y, neg2)};

        const int k0 = (lane & 1) * 4;            // this thread's 4 sub-centers
        const ulonglong2* cb = (const ulonglong2*)(s_in + (size_t)bo * ISTRIDE + k0 * 16);
        const float* nb = s_in + (size_t)bo * ISTRIDE + 128 + k0;

        float bd = FINF; int bk = k0;
        #pragma unroll
        for (int j = 0; j < 4; j++) {
            ulonglong2 r0 = cb[4*j], r1 = cb[4*j+1], r2 = cb[4*j+2], r3 = cb[4*j+3];
            u64 s = ffma2(py[0], r0.x, packf2(nb[j], 0.f));
            s = ffma2(py[1], r0.y, s);
            s = ffma2(py[2], r1.x, s);
            s = ffma2(py[3], r1.y, s);
            s = ffma2(py[4], r2.x, s);
            s = ffma2(py[5], r2.y, s);
            s = ffma2(py[6], r3.x, s);
            s = ffma2(py[7], r3.y, s);
            float dd = hsum2(s);
            if (dd < bd) { bd = dd; bk = k0 + j; }
        }

        u64 kk = dkey(bd, bo * NCPC + bk);
        kk = umin64(kk, __shfl_xor_sync(0xffffffffu, kk, 1));
        if (valid && (lane & 1) == 0)
            out[pt] = (float)(uint32_t)kk;
    }
}

extern "C" void kernel_launch(void* const* d_in, const int* in_sizes, int n_in,
                              void* d_out, int out_size)
{
    // Bind inputs by unique element counts (robust to metadata ordering).
    const float* x  = 0; const float* co = 0; const float* ci = 0;
    long long x_elems = 0;
    for (int i = 0; i < n_in; i++) {
        int sz = in_sizes[i];
        if (sz == NCC * 16)              co = (const float*)d_in[i];
        else if (sz == NCC * NCPC * 16)  ci = (const float*)d_in[i];
        else { x = (const float*)d_in[i]; x_elems = sz; }
    }
    if (!x)  { x  = (const float*)d_in[0]; x_elems = in_sizes[0]; }
    if (!co)   co = (const float*)d_in[1];
    if (!ci)   ci = (const float*)d_in[2];

    float* out = (float*)d_out;
    int n = (int)(x_elems / 32);
    if (n <= 0 || n > out_size) n = out_size;

    int blocks = 444;   // 148 SMs x 3 CTAs of 256 thr; grid-stride over 16-pt tiles
    cluster_hmma_kernel<<<blocks, 256>>>(x, co, ci, out, n);
}

// round 16
// speedup vs baseline: 1.9293x; 1.1754x over previous
#include <cuda_runtime.h>
#include <cuda_bf16.h>
#include <stdint.h>

#define NCC   64
#define NCPC  8
#define FINF  3.402823466e38f
#define ISTRIDE 140                   // inner o-row: 128 data + 8 norms + 4 pad floats

typedef unsigned long long u64;

// ---------- f32x2 helpers (inner stage, R9-proven exact path) ----------
__device__ __forceinline__ u64 ffma2(u64 a, u64 b, u64 c) {
    u64 d; asm("fma.rn.f32x2 %0, %1, %2, %3;" : "=l"(d) : "l"(a), "l"(b), "l"(c)); return d;
}
__device__ __forceinline__ u64 fmul2(u64 a, u64 b) {
    u64 d; asm("mul.rn.f32x2 %0, %1, %2;" : "=l"(d) : "l"(a), "l"(b)); return d;
}
__device__ __forceinline__ float hsum2(u64 v) {
    float lo, hi; asm("mov.b64 {%0, %1}, %2;" : "=f"(lo), "=f"(hi) : "l"(v)); return lo + hi;
}
__device__ __forceinline__ u64 packf2(float lo, float hi) {
    u64 r; asm("mov.b64 %0, {%1, %2};" : "=l"(r) : "f"(lo), "f"(hi)); return r;
}

// ---------- 3-way bf16 split (carries ~24 mantissa bits) ----------
__device__ __forceinline__ void split3(float vx, float vy,
                                       uint32_t& s1, uint32_t& s2, uint32_t& s3) {
    __nv_bfloat162 h1 = __float22bfloat162_rn(make_float2(vx, vy));
    float2 f1 = __bfloat1622float2(h1);
    float rx = vx - f1.x, ry = vy - f1.y;
    __nv_bfloat162 h2 = __float22bfloat162_rn(make_float2(rx, ry));
    float2 f2 = __bfloat1622float2(h2);
    __nv_bfloat162 h3 = __float22bfloat162_rn(make_float2(rx - f2.x, ry - f2.y));
    s1 = *reinterpret_cast<uint32_t*>(&h1);
    s2 = *reinterpret_cast<uint32_t*>(&h2);
    s3 = *reinterpret_cast<uint32_t*>(&h3);
}
__device__ __forceinline__ void mma16816(float& d0, float& d1, float& d2, float& d3,
                                         uint32_t a0, uint32_t a1, uint32_t a2, uint32_t a3,
                                         uint32_t b0, uint32_t b1) {
    asm volatile("mma.sync.aligned.m16n8k16.row.col.f32.bf16.bf16.f32 "
                 "{%0,%1,%2,%3}, {%4,%5,%6,%7}, {%8,%9}, {%0,%1,%2,%3};"
                 : "+f"(d0), "+f"(d1), "+f"(d2), "+f"(d3)
                 : "r"(a0), "r"(a1), "r"(a2), "r"(a3), "r"(b0), "r"(b1));
}

// monotone float->uint map packed with index: u64 min == (dist, then smaller idx)
__device__ __forceinline__ u64 dkey(float f, int i) {
    uint32_t b = __float_as_uint(f);
    uint32_t m = b ^ ((uint32_t)((int)b >> 31) | 0x80000000u);
    return ((u64)m << 32) | (uint32_t)i;
}
__device__ __forceinline__ u64 umin64(u64 a, u64 b) { return a < b ? a : b; }
__device__ __forceinline__ u64 shflx64(u64 v, int m) {
    uint32_t lo = (uint32_t)v, hi = (uint32_t)(v >> 32);
    lo = __shfl_xor_sync(0xffffffffu, lo, m);
    hi = __shfl_xor_sync(0xffffffffu, hi, m);
    return ((u64)hi << 32) | lo;
}

__global__ void __launch_bounds__(256, 2)
cluster_hmma_kernel(const float* __restrict__ x,
                    const float* __restrict__ co,
                    const float* __restrict__ ci,
                    float* __restrict__ out, int n)
{
    __shared__ float s_on[NCC];
    // inner centers, R9 layout: row o = {128 data floats | 8 norms | 4 pad}
    __shared__ __align__(16) float s_in[NCC * ISTRIDE];

    const int tid  = threadIdx.x;
    const int lane = tid & 31;
    const int wid  = tid >> 5;
    const int kq   = (lane & 3) * 2;      // k-pair offset of this lane's fragments
    const int nB   = lane >> 2;           // B column within an 8-center block

    // outer norms (exact fp32, sequential d — matches reference decisions)
    if (tid < NCC) {
        const float* cp = co + tid * 16;
        float s = 0.f;
        #pragma unroll
        for (int d = 0; d < 16; d++) s += cp[d] * cp[d];
        s_on[tid] = s;
    }
    // inner centers -> smem (coalesced), then norms into the pad region
    for (int idx = tid; idx < NCC * NCPC * 16; idx += 256) {
        int o = idx >> 7, r = idx & 127;
        s_in[o * ISTRIDE + r] = ci[idx];
    }
    __syncthreads();
    for (int e = tid; e < NCC * NCPC; e += 256) {
        int o = e >> 3, k = e & 7;
        const float* cp = s_in + o * ISTRIDE + k * 16;
        float s = 0.f;
        #pragma unroll
        for (int d = 0; d < 16; d++) s += cp[d] * cp[d];
        s_in[o * ISTRIDE + 128 + k] = s;
    }
    __syncthreads();

    // Loop-invariant B fragments IN REGISTERS (48 regs; inner stage is lean
    // enough now that this fits under the 128-reg budget without spilling).
    uint32_t bf1[8][2], bf2[8][2], bf3[8][2];
    #pragma unroll
    for (int b = 0; b < 8; b++) {
        const float* cb = co + (size_t)(8 * b + nB) * 16;
        float2 g0 = *(const float2*)(cb + kq);
        float2 g1 = *(const float2*)(cb + kq + 8);
        split3(g0.x, g0.y, bf1[b][0], bf2[b][0], bf3[b][0]);
        split3(g1.x, g1.y, bf1[b][1], bf2[b][1], bf3[b][1]);
    }

    const int ntile = (n + 15) >> 4;
    const int gw = blockIdx.x * 8 + wid;
    const int nw = gridDim.x * 8;
    const u64 neg2 = packf2(-2.f, -2.f);
    const float* s_on_kq = s_on + kq;     // lane-specific norm base

    for (int t = gw; t < ntile; t += nw) {
        const int base = t * 16;

        // ---- A fragments: rows = points, values = -2*x1, 3-way split ----
        int rlo = base + (lane >> 2);     if (rlo >= n) rlo = n - 1;
        int rhi = rlo + 8;                if (rhi >= n) rhi = n - 1;
        const float* xl = x + (size_t)rlo * 32;
        const float* xh = x + (size_t)rhi * 32;
        float2 fa = *(const float2*)(xl + kq);
        float2 fb = *(const float2*)(xh + kq);
        float2 fc = *(const float2*)(xl + kq + 8);
        float2 fd = *(const float2*)(xh + kq + 8);

        uint32_t a1[4], a2[4], a3[4];
        split3(-2.f * fa.x, -2.f * fa.y, a1[0], a2[0], a3[0]);
        split3(-2.f * fb.x, -2.f * fb.y, a1[1], a2[1], a3[1]);
        split3(-2.f * fc.x, -2.f * fc.y, a1[2], a2[2], a3[2]);
        split3(-2.f * fd.x, -2.f * fd.y, a1[3], a2[3], a3[3]);

        // ---- outer distances: 6-term split MMA (same order as R13-R15) ----
        float bdl = FINF, bdh = FINF;
        int   bcl = 0,    bch = 0;

        #pragma unroll
        for (int b = 0; b < 8; b++) {
            float d0 = 0.f, d1 = 0.f, d2 = 0.f, d3 = 0.f;
            mma16816(d0,d1,d2,d3, a3[0],a3[1],a3[2],a3[3], bf1[b][0], bf1[b][1]); // a3*b1
            mma16816(d0,d1,d2,d3, a2[0],a2[1],a2[2],a2[3], bf2[b][0], bf2[b][1]); // a2*b2
            mma16816(d0,d1,d2,d3, a1[0],a1[1],a1[2],a1[3], bf3[b][0], bf3[b][1]); // a1*b3
            mma16816(d0,d1,d2,d3, a2[0],a2[1],a2[2],a2[3], bf1[b][0], bf1[b][1]); // a2*b1
            mma16816(d0,d1,d2,d3, a1[0],a1[1],a1[2],a1[3], bf2[b][0], bf2[b][1]); // a1*b2
            mma16816(d0,d1,d2,d3, a1[0],a1[1],a1[2],a1[3], bf1[b][0], bf1[b][1]); // a1*b1

            float2 nr = *(const float2*)(s_on_kq + 8 * b);   // broadcast-cheap LDS
            float e0 = d0 + nr.x, e1 = d1 + nr.y;   // row lo, cols 8b+kq, +1
            float e2 = d2 + nr.x, e3 = d3 + nr.y;   // row hi
            int c0 = 8 * b + kq, c1 = c0 + 1;
            if (e0 < bdl) { bdl = e0; bcl = c0; }
            if (e1 < bdl) { bdl = e1; bcl = c1; }
            if (e2 < bdh) { bdh = e2; bch = c0; }
            if (e3 < bdh) { bdh = e3; bch = c1; }
        }

        // quad reduction over the 4 lanes holding this row's columns
        u64 klo = dkey(bdl, bcl), khi = dkey(bdh, bch);
        klo = umin64(klo, shflx64(klo, 1));
        khi = umin64(khi, shflx64(khi, 1));
        klo = umin64(klo, shflx64(klo, 2));
        khi = umin64(khi, shflx64(khi, 2));
        uint32_t col_lo = (uint32_t)klo, col_hi = (uint32_t)khi;

        // ---- redistribute: 2 threads per point for the inner stage ----
        const int r  = lane >> 1;                 // 0..15
        const int pt = base + r;
        const bool valid = (pt < n);
        const int  ptc = valid ? pt : (n - 1);
        const int  src = (r & 7) * 4;             // lane holding row r's argmin
        uint32_t blo = __shfl_sync(0xffffffffu, col_lo, src);
        uint32_t bhi = __shfl_sync(0xffffffffu, col_hi, src);
        const int bo = (r < 8) ? (int)blo : (int)bhi;

        // ---- x2 load, deduped: even lane loads dims 16-23, odd 24-31;
        //      lane-pair shuffle reconstructs the full row in both. ----
        const ulonglong2* qh = (const ulonglong2*)(x + (size_t)ptc * 32 + 16 + (lane & 1) * 8);
        ulonglong2 qa = qh[0], qb = qh[1];        // my 32B half
        u64 oa_x = shflx64(qa.x, 1), oa_y = shflx64(qa.y, 1);
        u64 ob_x = shflx64(qb.x, 1), ob_y = shflx64(qb.y, 1);
        u64 h0, h1, h2, h3, h4, h5, h6, h7;       // dims 16..31 as u64 pairs
        if ((lane & 1) == 0) { h0=qa.x; h1=qa.y; h2=qb.x; h3=qb.y; h4=oa_x; h5=oa_y; h6=ob_x; h7=ob_y; }
        else                 { h0=oa_x; h1=oa_y; h2=ob_x; h3=ob_y; h4=qa.x; h5=qa.y; h6=qb.x; h7=qb.y; }

        u64 py[8] = {fmul2(h0, neg2), fmul2(h1, neg2), fmul2(h2, neg2), fmul2(h3, neg2),
                     fmul2(h4, neg2), fmul2(h5, neg2), fmul2(h6, neg2), fmul2(h7, neg2)};

        // ---- inner argmin: acc = (norm,0) + sum (-2x2)*c, centers from SMEM ----
        const int k0 = (lane & 1) * 4;            // this thread's 4 sub-centers
        const ulonglong2* cb = (const ulonglong2*)(s_in + (size_t)bo * ISTRIDE + k0 * 16);
        const float* nb = s_in + (size_t)bo * ISTRIDE + 128 + k0;

        float bd = FINF; int bk = k0;
        #pragma unroll
        for (int j = 0; j < 4; j++) {
            ulonglong2 r0 = cb[4*j], r1 = cb[4*j+1], r2 = cb[4*j+2], r3 = cb[4*j+3];
            u64 s = ffma2(py[0], r0.x, packf2(nb[j], 0.f));
            s = ffma2(py[1], r0.y, s);
            s = ffma2(py[2], r1.x, s);
            s = ffma2(py[3], r1.y, s);
            s = ffma2(py[4], r2.x, s);
            s = ffma2(py[5], r2.y, s);
            s = ffma2(py[6], r3.x, s);
            s = ffma2(py[7], r3.y, s);
            float dd = hsum2(s);
            if (dd < bd) { bd = dd; bk = k0 + j; }
        }

        u64 kk = dkey(bd, bo * NCPC + bk);
        kk = umin64(kk, shflx64(kk, 1));
        if (valid && (lane & 1) == 0)
            out[pt] = (float)(uint32_t)kk;
    }
}

extern "C" void kernel_launch(void* const* d_in, const int* in_sizes, int n_in,
                              void* d_out, int out_size)
{
    // Bind inputs by unique element counts (robust to metadata ordering).
    const float* x  = 0; const float* co = 0; const float* ci = 0;
    long long x_elems = 0;
    for (int i = 0; i < n_in; i++) {
        int sz = in_sizes[i];
        if (sz == NCC * 16)              co = (const float*)d_in[i];
        else if (sz == NCC * NCPC * 16)  ci = (const float*)d_in[i];
        else { x = (const float*)d_in[i]; x_elems = sz; }
    }
    if (!x)  { x  = (const float*)d_in[0]; x_elems = in_sizes[0]; }
    if (!co)   co = (const float*)d_in[1];
    if (!ci)   ci = (const float*)d_in[2];

    float* out = (float*)d_out;
    int n = (int)(x_elems / 32);
    if (n <= 0 || n > out_size) n = out_size;

    int blocks = 296;   // 148 SMs x 2 CTAs of 256 thr; grid-stride over 16-pt tiles
    cluster_hmma_kernel<<<blocks, 256>>>(x, co, ci, out, n);
}